// round 15
// baseline (speedup 1.0000x reference)
#include <cuda_runtime.h>

// Problem: B=1, L=768, D_SINGLE=384, D_PAIR=128
//   left  = s @ W[:384] + bias   (768x128)   [bias folded into left]
//   right = s @ W[384:]          (768x128)
//   out[i,j,f] = left[i,f] + right[j,f]      -> 768*768*128 fp32 = 302 MB
//
// FINAL champion (R5/R13, 65.95-66.3us band). Operating at the DRAM write
// floor: ~57us/replay for the 302MB output stream + ~9us boundary/proj.
// Hard-won constraints (each violated variant measured slower):
//  - Output stores MUST be 128-bit __stcs. Non-evict-first policy costs
//    +20us; and 256-bit (v8.b32) STG silently loses the streaming hint on
//    sm_103a -> same +20us (R6/R8/R14 all landed at 86.4us).
//  - Bcast geometry: 1 i-row/block, 8 warps = 8 consecutive j-rows/step
//    (contiguous 4KB write front), grid 4608 for occupancy. Any i-tiling
//    (TI_B=2 or 8) lowers DRAM% (R9/R11).
//  - Software-sync fusion loses (+2.5..+19us, R4/R10); PDL chaining is free.
//  - Proj compute tweaks are invisible (hidden under the previous replay's
//    L2->DRAM drain, R12) - keep the numerically tightest scalar-FMA form.
//
// Inputs (metadata order): s (768*384 f32), z (UNUSED), W (768*128 f32), bias (128 f32)

#define L_DIM 768
#define DS 384
#define DP 128
#define TI 6          // rows per proj block -> 128 blocks (single wave)

// scratch (no cudaMalloc allowed)
__device__ float g_left[L_DIM * DP];    // includes bias
__device__ float g_right[L_DIM * DP];

// ---------------------------------------------------------------------------
// Kernel 1: projections. 128 blocks x 256 threads.
// f = tid&127 output column, half = tid>>7 selects left/right.
// s staged in smem, consumed as float4 (warp-broadcast LDS.128).
// W scalar LDG, coalesced across the 128 f-threads (L2-hot).
// ---------------------------------------------------------------------------
__global__ __launch_bounds__(256) void proj_kernel(
    const float* __restrict__ s,     // [768, 384]
    const float* __restrict__ W,     // [768, 128]
    const float* __restrict__ bias)  // [128]
{
    __shared__ float s_sh[TI][DS];
    const int i0  = blockIdx.x * TI;
    const int tid = threadIdx.x;

    for (int idx = tid; idx < TI * DS; idx += 256) {
        int r = idx / DS, c = idx % DS;
        s_sh[r][c] = s[(size_t)(i0 + r) * DS + c];
    }
    __syncthreads();

    const int f    = tid & 127;
    const int half = tid >> 7;                    // 0 = left, 1 = right
    const float* Wcol = W + (size_t)(half ? DS : 0) * DP + f;

    float acc[TI];
#pragma unroll
    for (int ii = 0; ii < TI; ii++) acc[ii] = 0.f;

    const float4 (*s4)[DS / 4] = reinterpret_cast<const float4 (*)[DS / 4]>(s_sh);

#pragma unroll 4
    for (int k4 = 0; k4 < DS / 4; k4++) {
        const int kb = k4 * 4;
        float w0 = Wcol[(size_t)(kb + 0) * DP];
        float w1 = Wcol[(size_t)(kb + 1) * DP];
        float w2 = Wcol[(size_t)(kb + 2) * DP];
        float w3 = Wcol[(size_t)(kb + 3) * DP];
#pragma unroll
        for (int ii = 0; ii < TI; ii++) {
            float4 sv = s4[ii][k4];               // one LDS.128, warp-broadcast
            acc[ii] = fmaf(sv.x, w0, acc[ii]);
            acc[ii] = fmaf(sv.y, w1, acc[ii]);
            acc[ii] = fmaf(sv.z, w2, acc[ii]);
            acc[ii] = fmaf(sv.w, w3, acc[ii]);
        }
    }

    if (half == 0) {
        const float b = bias[f];
#pragma unroll
        for (int ii = 0; ii < TI; ii++)
            g_left[(size_t)(i0 + ii) * DP + f] = acc[ii] + b;
    } else {
#pragma unroll
        for (int ii = 0; ii < TI; ii++)
            g_right[(size_t)(i0 + ii) * DP + f] = acc[ii];
    }

    __syncthreads();
    __threadfence();
    cudaTriggerProgrammaticLaunchCompletion();
}

// ---------------------------------------------------------------------------
// Kernel 2: broadcast-add. out[i,j,f] = left[i,f] + right[j,f].
// grid = (6 j-chunks, 768 i). 256 threads: f4 = tid&31, jl = tid>>5.
// Per jj-step the 8 warps write 8 consecutive j rows = contiguous 4KB.
// 128-bit evict-first streaming stores; right[] stays L2-resident.
// ---------------------------------------------------------------------------
__global__ __launch_bounds__(256) void bcast_kernel(float* __restrict__ out)
{
    const int i   = blockIdx.y;
    const int j0  = blockIdx.x * 128;
    const int tid = threadIdx.x;
    const int f4  = tid & 31;
    const int jl  = tid >> 5;

    cudaGridDependencySynchronize();   // PDL: wait for proj's triggered stores

    const float4* left4  = reinterpret_cast<const float4*>(g_left);
    const float4* right4 = reinterpret_cast<const float4*>(g_right);
    float4* out4 = reinterpret_cast<float4*>(out);

    const float4 lv = left4[(size_t)i * 32 + f4];       // includes bias
    const size_t orow = ((size_t)i * L_DIM + j0) * 32 + f4;

#pragma unroll 4
    for (int jj = jl; jj < 128; jj += 8) {
        float4 rv = __ldg(right4 + (size_t)(j0 + jj) * 32 + f4);
        float4 o;
        o.x = lv.x + rv.x;
        o.y = lv.y + rv.y;
        o.z = lv.z + rv.z;
        o.w = lv.w + rv.w;
        __stcs(out4 + orow + (size_t)jj * 32, o);       // 128-bit evict-first
    }
}

// ---------------------------------------------------------------------------
extern "C" void kernel_launch(void* const* d_in, const int* in_sizes, int n_in,
                              void* d_out, int out_size)
{
    const float* s    = (const float*)d_in[0];
    // d_in[1] = z : intentionally unused (reference never reads it)
    const float* W    = (const float*)d_in[2];
    const float* bias = (const float*)d_in[3];
    float* out = (float*)d_out;

    proj_kernel<<<L_DIM / TI, 256>>>(s, W, bias);

    cudaLaunchConfig_t cfg = {};
    cfg.gridDim  = dim3(L_DIM / 128, L_DIM);   // (6, 768)
    cfg.blockDim = dim3(256, 1, 1);
    cfg.dynamicSmemBytes = 0;
    cfg.stream = 0;

    cudaLaunchAttribute attr;
    attr.id = cudaLaunchAttributeProgrammaticStreamSerialization;
    attr.val.programmaticStreamSerializationAllowed = 1;
    cfg.attrs = &attr;
    cfg.numAttrs = 1;

    cudaLaunchKernelEx(&cfg, bcast_kernel, out);
}

// round 16
// speedup vs baseline: 1.4695x; 1.4695x over previous
#include <cuda_runtime.h>

// Problem: B=1, L=768, D_SINGLE=384, D_PAIR=128
//   left  = s @ W[:384] + bias   (768x128)   [bias folded into left]
//   right = s @ W[384:]          (768x128)
//   out[i,j,f] = left[i,f] + right[j,f]      -> 768*768*128 fp32 = 302 MB
//
// CHAMPION (R5/R13, 65.95-66.3us band at nominal HBM clocks). R15 measured
// this exact binary at 97us with HBM throughput down 33% at identical SM
// metrics -> environmental outlier (clock state / co-tenant), resubmitted
// unchanged for re-verification.
//
// Operating at the DRAM write floor: ~57us/replay for the 302MB output
// stream + ~9us boundary/proj. Hard constraints (violations all measured):
//  - Output stores MUST be 128-bit __stcs: non-evict-first costs +20us, and
//    256-bit v8.b32 STG silently drops the streaming hint (R6/R8/R14: 86.4us).
//  - Bcast geometry: 1 i-row/block, 8 warps = 8 consecutive j-rows/step
//    (contiguous 4KB front), grid 4608. i-tiling lowers DRAM% (R9/R11).
//  - Software-sync fusion loses (R4/R10); PDL chaining is free (R5).
//  - Proj compute tweaks invisible (R12).
//
// Inputs (metadata order): s (768*384 f32), z (UNUSED), W (768*128 f32), bias (128 f32)

#define L_DIM 768
#define DS 384
#define DP 128
#define TI 6          // rows per proj block -> 128 blocks (single wave)

// scratch (no cudaMalloc allowed)
__device__ float g_left[L_DIM * DP];    // includes bias
__device__ float g_right[L_DIM * DP];

// ---------------------------------------------------------------------------
// Kernel 1: projections. 128 blocks x 256 threads.
// ---------------------------------------------------------------------------
__global__ __launch_bounds__(256) void proj_kernel(
    const float* __restrict__ s,     // [768, 384]
    const float* __restrict__ W,     // [768, 128]
    const float* __restrict__ bias)  // [128]
{
    __shared__ float s_sh[TI][DS];
    const int i0  = blockIdx.x * TI;
    const int tid = threadIdx.x;

    for (int idx = tid; idx < TI * DS; idx += 256) {
        int r = idx / DS, c = idx % DS;
        s_sh[r][c] = s[(size_t)(i0 + r) * DS + c];
    }
    __syncthreads();

    const int f    = tid & 127;
    const int half = tid >> 7;                    // 0 = left, 1 = right
    const float* Wcol = W + (size_t)(half ? DS : 0) * DP + f;

    float acc[TI];
#pragma unroll
    for (int ii = 0; ii < TI; ii++) acc[ii] = 0.f;

    const float4 (*s4)[DS / 4] = reinterpret_cast<const float4 (*)[DS / 4]>(s_sh);

#pragma unroll 4
    for (int k4 = 0; k4 < DS / 4; k4++) {
        const int kb = k4 * 4;
        float w0 = Wcol[(size_t)(kb + 0) * DP];
        float w1 = Wcol[(size_t)(kb + 1) * DP];
        float w2 = Wcol[(size_t)(kb + 2) * DP];
        float w3 = Wcol[(size_t)(kb + 3) * DP];
#pragma unroll
        for (int ii = 0; ii < TI; ii++) {
            float4 sv = s4[ii][k4];               // one LDS.128, warp-broadcast
            acc[ii] = fmaf(sv.x, w0, acc[ii]);
            acc[ii] = fmaf(sv.y, w1, acc[ii]);
            acc[ii] = fmaf(sv.z, w2, acc[ii]);
            acc[ii] = fmaf(sv.w, w3, acc[ii]);
        }
    }

    if (half == 0) {
        const float b = bias[f];
#pragma unroll
        for (int ii = 0; ii < TI; ii++)
            g_left[(size_t)(i0 + ii) * DP + f] = acc[ii] + b;
    } else {
#pragma unroll
        for (int ii = 0; ii < TI; ii++)
            g_right[(size_t)(i0 + ii) * DP + f] = acc[ii];
    }

    __syncthreads();
    __threadfence();
    cudaTriggerProgrammaticLaunchCompletion();
}

// ---------------------------------------------------------------------------
// Kernel 2: broadcast-add. out[i,j,f] = left[i,f] + right[j,f].
// grid = (6 j-chunks, 768 i). 256 threads: f4 = tid&31, jl = tid>>5.
// ---------------------------------------------------------------------------
__global__ __launch_bounds__(256) void bcast_kernel(float* __restrict__ out)
{
    const int i   = blockIdx.y;
    const int j0  = blockIdx.x * 128;
    const int tid = threadIdx.x;
    const int f4  = tid & 31;
    const int jl  = tid >> 5;

    cudaGridDependencySynchronize();   // PDL: wait for proj's triggered stores

    const float4* left4  = reinterpret_cast<const float4*>(g_left);
    const float4* right4 = reinterpret_cast<const float4*>(g_right);
    float4* out4 = reinterpret_cast<float4*>(out);

    const float4 lv = left4[(size_t)i * 32 + f4];       // includes bias
    const size_t orow = ((size_t)i * L_DIM + j0) * 32 + f4;

#pragma unroll 4
    for (int jj = jl; jj < 128; jj += 8) {
        float4 rv = __ldg(right4 + (size_t)(j0 + jj) * 32 + f4);
        float4 o;
        o.x = lv.x + rv.x;
        o.y = lv.y + rv.y;
        o.z = lv.z + rv.z;
        o.w = lv.w + rv.w;
        __stcs(out4 + orow + (size_t)jj * 32, o);       // 128-bit evict-first
    }
}

// ---------------------------------------------------------------------------
extern "C" void kernel_launch(void* const* d_in, const int* in_sizes, int n_in,
                              void* d_out, int out_size)
{
    const float* s    = (const float*)d_in[0];
    // d_in[1] = z : intentionally unused (reference never reads it)
    const float* W    = (const float*)d_in[2];
    const float* bias = (const float*)d_in[3];
    float* out = (float*)d_out;

    proj_kernel<<<L_DIM / TI, 256>>>(s, W, bias);

    cudaLaunchConfig_t cfg = {};
    cfg.gridDim  = dim3(L_DIM / 128, L_DIM);   // (6, 768)
    cfg.blockDim = dim3(256, 1, 1);
    cfg.dynamicSmemBytes = 0;
    cfg.stream = 0;

    cudaLaunchAttribute attr;
    attr.id = cudaLaunchAttributeProgrammaticStreamSerialization;
    attr.val.programmaticStreamSerializationAllowed = 1;
    cfg.attrs = &attr;
    cfg.numAttrs = 1;

    cudaLaunchKernelEx(&cfg, bcast_kernel, out);
}

// round 17
// speedup vs baseline: 1.4702x; 1.0005x over previous
#include <cuda_runtime.h>

// Problem: B=1, L=768, D_SINGLE=384, D_PAIR=128
//   left  = s @ W[:384] + bias   (768x128)   [bias folded into left]
//   right = s @ W[384:]          (768x128)
//   out[i,j,f] = left[i,f] + right[j,f]      -> 768*768*128 fp32 = 302 MB
//
// FINAL CHAMPION — verified 65.95/66.0/66.3/66.05us across four runs
// (plus one 97us environmental outlier, R15, reproduced away in R16).
// Operating at the HBM write-direction floor: 302MB/replay at ~5.2TB/s
// effective write BW (~57us) + ~9us proj/boundary exposure.
//
// Hard constraints, each established by a measured counterexample:
//  - Output stores MUST be 128-bit __stcs (evict-first). Write-back or any
//    evict_last policy costs +20us (R6/R8); 256-bit v8.b32 STG silently
//    DROPS the streaming hint on sm_103a -> same +20us (R14).
//  - Bcast geometry: 1 i-row/block, 8 warps = 8 consecutive j-rows per step
//    (contiguous 4KB write front), grid 4608 for ~86% occupancy. Any
//    i-tiling (TI_B=2/8) reduces achieved DRAM BW (R11/R9).
//  - Software-synchronized fusion loses (+2.5..+19us, R4/R10). PDL chaining
//    is free and keeps producers at full SM resources (R5).
//  - Proj compute optimizations are invisible — proj hides under the
//    previous replay's L2->DRAM drain (R12). Scalar-FMA form kept for the
//    tightest rel_err (4.7e-8).
//  - z input is never read by the reference; do not touch its 302MB.
//
// Inputs (metadata order): s (768*384 f32), z (UNUSED), W (768*128 f32), bias (128 f32)

#define L_DIM 768
#define DS 384
#define DP 128
#define TI 6          // rows per proj block -> 128 blocks (single wave)

// scratch (no cudaMalloc allowed)
__device__ float g_left[L_DIM * DP];    // includes bias
__device__ float g_right[L_DIM * DP];

// ---------------------------------------------------------------------------
// Kernel 1: projections. 128 blocks x 256 threads.
// f = tid&127 output column, half = tid>>7 selects left/right.
// s staged in smem, consumed as float4 (warp-broadcast LDS.128).
// W scalar LDG, coalesced across the 128 f-threads (L2-hot).
// ---------------------------------------------------------------------------
__global__ __launch_bounds__(256) void proj_kernel(
    const float* __restrict__ s,     // [768, 384]
    const float* __restrict__ W,     // [768, 128]
    const float* __restrict__ bias)  // [128]
{
    __shared__ float s_sh[TI][DS];
    const int i0  = blockIdx.x * TI;
    const int tid = threadIdx.x;

    for (int idx = tid; idx < TI * DS; idx += 256) {
        int r = idx / DS, c = idx % DS;
        s_sh[r][c] = s[(size_t)(i0 + r) * DS + c];
    }
    __syncthreads();

    const int f    = tid & 127;
    const int half = tid >> 7;                    // 0 = left, 1 = right
    const float* Wcol = W + (size_t)(half ? DS : 0) * DP + f;

    float acc[TI];
#pragma unroll
    for (int ii = 0; ii < TI; ii++) acc[ii] = 0.f;

    const float4 (*s4)[DS / 4] = reinterpret_cast<const float4 (*)[DS / 4]>(s_sh);

#pragma unroll 4
    for (int k4 = 0; k4 < DS / 4; k4++) {
        const int kb = k4 * 4;
        float w0 = Wcol[(size_t)(kb + 0) * DP];
        float w1 = Wcol[(size_t)(kb + 1) * DP];
        float w2 = Wcol[(size_t)(kb + 2) * DP];
        float w3 = Wcol[(size_t)(kb + 3) * DP];
#pragma unroll
        for (int ii = 0; ii < TI; ii++) {
            float4 sv = s4[ii][k4];               // one LDS.128, warp-broadcast
            acc[ii] = fmaf(sv.x, w0, acc[ii]);
            acc[ii] = fmaf(sv.y, w1, acc[ii]);
            acc[ii] = fmaf(sv.z, w2, acc[ii]);
            acc[ii] = fmaf(sv.w, w3, acc[ii]);
        }
    }

    if (half == 0) {
        const float b = bias[f];
#pragma unroll
        for (int ii = 0; ii < TI; ii++)
            g_left[(size_t)(i0 + ii) * DP + f] = acc[ii] + b;
    } else {
#pragma unroll
        for (int ii = 0; ii < TI; ii++)
            g_right[(size_t)(i0 + ii) * DP + f] = acc[ii];
    }

    __syncthreads();
    __threadfence();
    cudaTriggerProgrammaticLaunchCompletion();
}

// ---------------------------------------------------------------------------
// Kernel 2: broadcast-add. out[i,j,f] = left[i,f] + right[j,f].
// grid = (6 j-chunks, 768 i). 256 threads: f4 = tid&31, jl = tid>>5.
// Per jj-step the 8 warps write 8 consecutive j rows = contiguous 4KB.
// 128-bit evict-first streaming stores; right[] (393KB) stays L2-resident.
// ---------------------------------------------------------------------------
__global__ __launch_bounds__(256) void bcast_kernel(float* __restrict__ out)
{
    const int i   = blockIdx.y;
    const int j0  = blockIdx.x * 128;
    const int tid = threadIdx.x;
    const int f4  = tid & 31;
    const int jl  = tid >> 5;

    cudaGridDependencySynchronize();   // PDL: wait for proj's triggered stores

    const float4* left4  = reinterpret_cast<const float4*>(g_left);
    const float4* right4 = reinterpret_cast<const float4*>(g_right);
    float4* out4 = reinterpret_cast<float4*>(out);

    const float4 lv = left4[(size_t)i * 32 + f4];       // includes bias
    const size_t orow = ((size_t)i * L_DIM + j0) * 32 + f4;

#pragma unroll 4
    for (int jj = jl; jj < 128; jj += 8) {
        float4 rv = __ldg(right4 + (size_t)(j0 + jj) * 32 + f4);
        float4 o;
        o.x = lv.x + rv.x;
        o.y = lv.y + rv.y;
        o.z = lv.z + rv.z;
        o.w = lv.w + rv.w;
        __stcs(out4 + orow + (size_t)jj * 32, o);       // 128-bit evict-first
    }
}

// ---------------------------------------------------------------------------
extern "C" void kernel_launch(void* const* d_in, const int* in_sizes, int n_in,
                              void* d_out, int out_size)
{
    const float* s    = (const float*)d_in[0];
    // d_in[1] = z : intentionally unused (reference never reads it)
    const float* W    = (const float*)d_in[2];
    const float* bias = (const float*)d_in[3];
    float* out = (float*)d_out;

    proj_kernel<<<L_DIM / TI, 256>>>(s, W, bias);

    cudaLaunchConfig_t cfg = {};
    cfg.gridDim  = dim3(L_DIM / 128, L_DIM);   // (6, 768)
    cfg.blockDim = dim3(256, 1, 1);
    cfg.dynamicSmemBytes = 0;
    cfg.stream = 0;

    cudaLaunchAttribute attr;
    attr.id = cudaLaunchAttributeProgrammaticStreamSerialization;
    attr.val.programmaticStreamSerializationAllowed = 1;
    cfg.attrs = &attr;
    cfg.numAttrs = 1;

    cudaLaunchKernelEx(&cfg, bcast_kernel, out);
}